// round 16
// baseline (speedup 1.0000x reference)
#include <cuda_runtime.h>
#include <cuda_fp16.h>
#include <cstdint>
#include <cstddef>

// ---------------- problem constants ----------------
constexpr int N_BATCH = 256;
constexpr int C  = 128;
constexpr int L0 = 1024;
constexpr int L1 = 505;
constexpr int L2 = 247;
constexpr int L3 = 121;
constexpr int L4 = 59;
constexpr int D  = C * L4;     // 7552
constexpr int KC = 64;

// padded sequence lengths (rows >= L stay zero forever: epilogues never write them)
constexpr int LP0 = 1040;   // conv1 window reads to 2*511+14 = 1036
constexpr int LP1 = 528;    // conv2 reads to 2*255+11 = 521
constexpr int LP2 = 264;    // conv3 reads to 2*127+6  = 260
constexpr int LP3 = 136;    // conv4 reads to 2*63+3   = 129
constexpr int LP4 = 64;     // h4 (59 valid)

// ---------------- device buffers (zero-initialized; pads stay 0) ----------
__device__ __align__(1024) __half g_x [(size_t)N_BATCH * LP0 * C];
__device__ __align__(1024) __half g_h1[(size_t)N_BATCH * LP1 * C];
__device__ __align__(1024) __half g_h2[(size_t)N_BATCH * LP2 * C];
__device__ __align__(1024) __half g_h3[(size_t)N_BATCH * LP3 * C];
__device__ __align__(1024) __half g_h4[(size_t)N_BATCH * LP4 * C];
// weights prepacked: per tap k, [s(8)][ntq(8)][lane(32)][8 halves] = 16384 halves
__device__ __align__(1024) __half g_wk[(15 + 12 + 7 + 4) * 16384];
// centers as half, permuted to [j][l*128+c] to match h4 layout
__device__ __align__(1024) __half g_cenh[(size_t)KC * D];

constexpr int WKB1 = 0;           // k-block offsets (units of 16384 halves)
constexpr int WKB2 = 15;
constexpr int WKB3 = 27;
constexpr int WKB4 = 34;
constexpr int W_ELEMS = 38 * 16384;   // 622592

// ---------------- helpers ----------------
__device__ __forceinline__ uint32_t smem_u32(const void* p) {
    uint32_t a;
    asm("{ .reg .u64 t; cvta.to.shared.u64 t, %1; cvt.u32.u64 %0, t; }"
        : "=r"(a) : "l"(p));
    return a;
}
__device__ __forceinline__ void cp16(void* dst, const void* src) {
    unsigned d = (unsigned)__cvta_generic_to_shared(dst);
    asm volatile("cp.async.ca.shared.global [%0], [%1], 16;"
                 :: "r"(d), "l"(src) : "memory");
}
#define CP_COMMIT() asm volatile("cp.async.commit_group;" ::: "memory")
#define CP_WAIT(n)  asm volatile("cp.async.wait_group %0;" :: "n"(n) : "memory")

__device__ __forceinline__ void ldsm4(uint32_t* a, uint32_t addr) {
    asm volatile("ldmatrix.sync.aligned.m8n8.x4.shared.b16 {%0,%1,%2,%3}, [%4];"
                 : "=r"(a[0]), "=r"(a[1]), "=r"(a[2]), "=r"(a[3]) : "r"(addr));
}
__device__ __forceinline__ void mma16(float* c, const uint32_t* a,
                                      uint32_t b0, uint32_t b1) {
    asm volatile(
        "mma.sync.aligned.m16n8k16.row.col.f32.f16.f16.f32 "
        "{%0,%1,%2,%3}, {%4,%5,%6,%7}, {%8,%9}, {%0,%1,%2,%3};"
        : "+f"(c[0]), "+f"(c[1]), "+f"(c[2]), "+f"(c[3])
        : "r"(a[0]), "r"(a[1]), "r"(a[2]), "r"(a[3]), "r"(b0), "r"(b1));
}

// ---------------------------------------------------------------------------
// Pre-pass 1: x [n][c][l] fp32 -> [n][l(pad)][c] half
// ---------------------------------------------------------------------------
__global__ void transpose_x(const float* __restrict__ x, __half* __restrict__ o) {
    __shared__ float t[32][33];
    int n = blockIdx.z, c0 = blockIdx.y * 32, l0 = blockIdx.x * 32;
    int tx = threadIdx.x, ty = threadIdx.y;
    #pragma unroll
    for (int i = 0; i < 4; i++)
        t[ty + 8 * i][tx] = x[((size_t)n * C + c0 + ty + 8 * i) * L0 + l0 + tx];
    __syncthreads();
    #pragma unroll
    for (int i = 0; i < 4; i++)
        o[((size_t)n * LP0 + l0 + ty + 8 * i) * C + c0 + tx] =
            __float2half(t[tx][ty + 8 * i]);
}

// ---------------------------------------------------------------------------
// Pre-pass 2 (fused): pack all weights into per-tap B-fragment order + centers
// to half. B-frag map (validated R14/15): per (s, ntq, lane, h):
//   nt = 2*ntq + (h>>2); hh = h&3; ic = 16*s + 2*(lane&3) + (hh&1) + 8*(hh>>1);
//   oc = nt*8 + (lane>>2)
// ---------------------------------------------------------------------------
__global__ void pack_all(const float* __restrict__ w1, const float* __restrict__ w2,
                         const float* __restrict__ w3, const float* __restrict__ w4,
                         const float* __restrict__ cen,
                         __half* __restrict__ wk, __half* __restrict__ cenh)
{
    int i = blockIdx.x * 256 + threadIdx.x;
    if (i < W_ELEMS) {
        int kb = i >> 14;
        int r  = i & 16383;
        const float* w; int k, K;
        if      (kb < WKB2) { w = w1; k = kb;        K = 15; }
        else if (kb < WKB3) { w = w2; k = kb - WKB2; K = 12; }
        else if (kb < WKB4) { w = w3; k = kb - WKB3; K = 7;  }
        else                { w = w4; k = kb - WKB4; K = 4;  }
        int s    = r >> 11;
        int ntq  = (r >> 8) & 7;
        int lane = (r >> 3) & 31;
        int h    = r & 7;
        int nt   = 2 * ntq + (h >> 2);
        int hh   = h & 3;
        int ic   = 16 * s + 2 * (lane & 3) + (hh & 1) + 8 * (hh >> 1);
        int oc   = nt * 8 + (lane >> 2);
        wk[i] = __float2half(w[((size_t)oc * C + ic) * K + k]);
    } else {
        int j = i - W_ELEMS;
        if (j >= KC * D) return;
        int jc = j / D;
        int r  = j - jc * D;
        int l  = r >> 7;
        int c  = r & 127;
        cenh[j] = __float2half(cen[(size_t)jc * D + c * L4 + l]);
    }
}

// ---------------------------------------------------------------------------
// fp16 mma conv (stride 2, VALID). CTA: MT=32*MTILES pos x 128 oc, one sample.
// A window (2*MT+K-1 rows x 128 ic) resident in SMEM, XOR-swizzled for
// conflict-free stride-2 ldmatrix. Tap loop with B (32KB/tap) double-buffered.
// 8 warps = 2(M) x 4(N: 32 oc); warp tile = MTILES m16-tiles x 32 oc.
// ---------------------------------------------------------------------------
template<int K, int L_OUT, int LP_IN, int LP_OUT, int MTILES, bool RELU>
__global__ void __launch_bounds__(256)
conv_mma(const __half* __restrict__ xin, const __half* __restrict__ wpk,
         const float* __restrict__ bias, __half* __restrict__ out)
{
    constexpr int MT     = 32 * MTILES;
    constexpr int WM     = 16 * MTILES;       // warp M extent (pos)
    constexpr int WR     = 2 * MT + K - 1;    // window rows
    constexpr int ABYTES = WR * 256;          // [WR][128 ic halves] swizzled
    constexpr int BBYTES = 32768;             // one tap: 128ic x 128oc half

    extern __shared__ __align__(16) char sm[];
    char* bbuf[2] = { sm + ABYTES, sm + ABYTES + BBYTES };

    const int tid  = threadIdx.x;
    const int w    = tid >> 5;
    const int lane = tid & 31;
    const int wm   = w & 1;         // M half
    const int wn   = w >> 1;        // N quarter (32 oc)
    const int g8   = lane >> 2;
    const int tig  = lane & 3;
    const int n    = blockIdx.y;
    const int p0   = blockIdx.x * MT;

    float acc[MTILES][4][4];
    #pragma unroll
    for (int m = 0; m < MTILES; m++)
        #pragma unroll
        for (int jn = 0; jn < 4; jn++)
            #pragma unroll
            for (int r = 0; r < 4; r++) acc[m][jn][r] = 0.0f;

    // ---- stage A window once (swizzled) ----
    {
        const __half* asrc = xin + ((size_t)n * LP_IN + 2 * p0) * C;
        #pragma unroll 1
        for (int j = tid; j < WR * 16; j += 256) {
            int r = j >> 4, t = j & 15;
            int ts = t ^ ((r >> 1) & 7);
            cp16(sm + r * 256 + ts * 16, asrc + (size_t)r * C + t * 8);
        }
    }
    CP_COMMIT();

    auto stageB = [&](int k, char* buf) {
        const __half* bsrc = wpk + (size_t)k * 16384;
        #pragma unroll 1
        for (int j = tid; j < 2048; j += 256)
            cp16(buf + j * 16, bsrc + j * 8);
    };
    stageB(0, bbuf[0]); CP_COMMIT();
    stageB(1, bbuf[1]); CP_COMMIT();
    CP_WAIT(1);             // A + B0 landed
    __syncthreads();

    const uint32_t abase = smem_u32(sm);

    #pragma unroll 1
    for (int k = 0; k < K; k++) {
        const char* bb = bbuf[k & 1];
        #pragma unroll
        for (int s = 0; s < 8; s++) {
            uint32_t a[MTILES][4];
            #pragma unroll
            for (int m = 0; m < MTILES; m++) {
                int rw = 2 * (wm * WM + m * 16 + (lane & 15)) + k;
                int ch = (s * 2 + (lane >> 4)) ^ ((rw >> 1) & 7);
                ldsm4(a[m], abase + (uint32_t)rw * 256 + (uint32_t)ch * 16);
            }
            #pragma unroll
            for (int q = 0; q < 2; q++) {
                uint4 bv = *(const uint4*)(bb +
                    ((size_t)((s * 8 + 2 * wn + q) * 32 + lane)) * 16);
                #pragma unroll
                for (int m = 0; m < MTILES; m++) {
                    mma16(acc[m][2 * q],     a[m], bv.x, bv.y);
                    mma16(acc[m][2 * q + 1], a[m], bv.z, bv.w);
                }
            }
        }
        __syncthreads();                       // done reading bbuf[k&1]
        if (k + 2 < K) {
            stageB(k + 2, bbuf[k & 1]); CP_COMMIT();
            CP_WAIT(1); __syncthreads();       // B[k+1] ready
        } else if (k + 1 < K) {
            CP_WAIT(0); __syncthreads();       // last B ready
        }
    }

    // ---- epilogue: bias + LeakyReLU, half2 (oc-pair) stores to [n][pos][c]
    float bv0[4], bv1[4];
    #pragma unroll
    for (int jn = 0; jn < 4; jn++) {
        int oc = (wn * 4 + jn) * 8 + 2 * tig;
        bv0[jn] = bias[oc];
        bv1[jn] = bias[oc + 1];
    }
    #pragma unroll
    for (int m = 0; m < MTILES; m++) {
        #pragma unroll
        for (int jn = 0; jn < 4; jn++) {
            const int oc = (wn * 4 + jn) * 8 + 2 * tig;
            #pragma unroll
            for (int r = 0; r < 2; r++) {
                const int pos = p0 + wm * WM + m * 16 + g8 + 8 * r;
                if (pos < L_OUT) {
                    float v0 = acc[m][jn][2 * r]     + bv0[jn];
                    float v1 = acc[m][jn][2 * r + 1] + bv1[jn];
                    if (RELU) {
                        v0 = (v0 > 0.0f) ? v0 : 0.1f * v0;
                        v1 = (v1 > 0.0f) ? v1 : 0.1f * v1;
                    }
                    *(__half2*)(out + ((size_t)n * LP_OUT + pos) * C + oc) =
                        __floats2half2_rn(v0, v1);
                }
            }
        }
    }
}

// ---------------------------------------------------------------------------
// Distance + Student-t soft assignment (alpha=1). NS=4 samples per CTA,
// half z (contiguous copy from h4) + half centers (prepermuted).
// ---------------------------------------------------------------------------
constexpr int NS = 4;

__global__ void __launch_bounds__(256)
dist_kernel(const __half* __restrict__ z, const __half* __restrict__ cenh,
            float* __restrict__ q)
{
    extern __shared__ __align__(16) __half zh[];   // [NS][D]
    __shared__ float d2s[KC][NS];
    __shared__ float qv[NS][KC];
    __shared__ float ssum[NS];

    const int tid = threadIdx.x;
    const int n0  = blockIdx.x * NS;

    #pragma unroll
    for (int ns = 0; ns < NS; ns++) {
        const uint4* src = (const uint4*)(z + (size_t)(n0 + ns) * LP4 * C);
        uint4* dst = (uint4*)(zh + ns * D);
        for (int j = tid; j < D / 8; j += 256) dst[j] = src[j];
    }
    __syncthreads();

    const int warp = tid >> 5;
    const int lane = tid & 31;

    #pragma unroll
    for (int cc = 0; cc < 8; cc++) {
        const int c = warp * 8 + cc;
        const __half2* cr = (const __half2*)(cenh + (size_t)c * D);
        float s[NS];
        #pragma unroll
        for (int ns = 0; ns < NS; ns++) s[ns] = 0.0f;
        #pragma unroll 2
        for (int idx = lane; idx < D / 2; idx += 32) {
            float2 cf = __half22float2(cr[idx]);
            #pragma unroll
            for (int ns = 0; ns < NS; ns++) {
                float2 a = __half22float2(
                    ((const __half2*)(zh + ns * D))[idx]);
                float d0 = a.x - cf.x, d1 = a.y - cf.y;
                s[ns] = fmaf(d0, d0, s[ns]);
                s[ns] = fmaf(d1, d1, s[ns]);
            }
        }
        #pragma unroll
        for (int ns = 0; ns < NS; ns++) {
            #pragma unroll
            for (int off = 16; off; off >>= 1)
                s[ns] += __shfl_xor_sync(0xffffffffu, s[ns], off);
            if (lane == 0) d2s[c][ns] = s[ns];
        }
    }
    __syncthreads();

    if (tid < NS * KC) {
        int ns = tid >> 6, c = tid & 63;
        qv[ns][c] = 1.0f / (1.0f + d2s[c][ns]);
    }
    __syncthreads();

    if (tid < NS * 32) {
        int ns = tid >> 5, l = tid & 31;
        float s = qv[ns][l] + qv[ns][l + 32];
        #pragma unroll
        for (int off = 16; off; off >>= 1)
            s += __shfl_xor_sync(0xffffffffu, s, off);
        if (l == 0) ssum[ns] = s;
    }
    __syncthreads();

    if (tid < NS * KC) {
        int ns = tid >> 6, c = tid & 63;
        q[(size_t)(n0 + ns) * KC + c] = qv[ns][c] / ssum[ns];
    }
}

// ---------------------------------------------------------------------------
// Host side
// ---------------------------------------------------------------------------
template<int K, int MTILES>
static constexpr int conv_smem() {
    return (2 * 32 * MTILES + K - 1) * 256 + 2 * 32768;
}

extern "C" void kernel_launch(void* const* d_in, const int* in_sizes, int n_in,
                              void* d_out, int out_size)
{
    const float* x   = (const float*)d_in[0];
    const float* w1  = (const float*)d_in[1];
    const float* b1  = (const float*)d_in[2];
    const float* w2  = (const float*)d_in[3];
    const float* b2  = (const float*)d_in[4];
    const float* w3  = (const float*)d_in[5];
    const float* b3  = (const float*)d_in[6];
    const float* w4  = (const float*)d_in[7];
    const float* b4  = (const float*)d_in[8];
    const float* cen = (const float*)d_in[9];
    float* q = (float*)d_out;

    __half* xh;  cudaGetSymbolAddress((void**)&xh,  g_x);
    __half* h1;  cudaGetSymbolAddress((void**)&h1,  g_h1);
    __half* h2;  cudaGetSymbolAddress((void**)&h2,  g_h2);
    __half* h3;  cudaGetSymbolAddress((void**)&h3,  g_h3);
    __half* h4;  cudaGetSymbolAddress((void**)&h4,  g_h4);
    __half* wk;  cudaGetSymbolAddress((void**)&wk,  g_wk);
    __half* ch;  cudaGetSymbolAddress((void**)&ch,  g_cenh);

    cudaFuncSetAttribute(conv_mma<15, L1, LP0, LP1, 4, true>,
        cudaFuncAttributeMaxDynamicSharedMemorySize, conv_smem<15, 4>());
    cudaFuncSetAttribute(conv_mma<12, L2, LP1, LP2, 4, true>,
        cudaFuncAttributeMaxDynamicSharedMemorySize, conv_smem<12, 4>());
    cudaFuncSetAttribute(conv_mma<7,  L3, LP2, LP3, 4, true>,
        cudaFuncAttributeMaxDynamicSharedMemorySize, conv_smem<7, 4>());
    cudaFuncSetAttribute(conv_mma<4,  L4, LP3, LP4, 2, false>,
        cudaFuncAttributeMaxDynamicSharedMemorySize, conv_smem<4, 2>());
    cudaFuncSetAttribute(dist_kernel,
        cudaFuncAttributeMaxDynamicSharedMemorySize, NS * D * 2);

    // pre-passes
    transpose_x<<<dim3(L0 / 32, C / 32, N_BATCH), dim3(32, 8)>>>(x, xh);
    {
        int tot = W_ELEMS + KC * D;
        pack_all<<<(tot + 255) / 256, 256>>>(w1, w2, w3, w4, cen, wk, ch);
    }

    // conv stack (fp16 tensor-core mma, fp32 accumulate)
    conv_mma<15, L1, LP0, LP1, 4, true><<<dim3(4, N_BATCH), 256, conv_smem<15, 4>()>>>(
        xh, wk + (size_t)WKB1 * 16384, b1, h1);
    conv_mma<12, L2, LP1, LP2, 4, true><<<dim3(2, N_BATCH), 256, conv_smem<12, 4>()>>>(
        h1, wk + (size_t)WKB2 * 16384, b2, h2);
    conv_mma<7,  L3, LP2, LP3, 4, true><<<dim3(1, N_BATCH), 256, conv_smem<7, 4>()>>>(
        h2, wk + (size_t)WKB3 * 16384, b3, h3);
    conv_mma<4,  L4, LP3, LP4, 2, false><<<dim3(1, N_BATCH), 256, conv_smem<4, 2>()>>>(
        h3, wk + (size_t)WKB4 * 16384, b4, h4);

    dist_kernel<<<N_BATCH / NS, 256, NS * D * 2>>>(h4, ch, q);
}